// round 13
// baseline (speedup 1.0000x reference)
#include <cuda_runtime.h>
#include <math.h>
#include <stdint.h>

#define NB   262144
#define H1C  128
#define H2C  256
#define H3C  200
#define GC   25
#define DC   4
#define GDC  100

// ---------------------------------------------------------- device scratch
__device__ float g_W2T[128 * 256];      // [k][n]
__device__ float g_W3T[256 * 208];      // [k][n], n padded 200->208
__device__ float g_WpT[200 * 104];      // [k][n], n padded 100->104

// ------------------------------------------------------------ f32x2 helpers
__device__ __forceinline__ uint64_t pk2(float x, float y) {
    uint64_t r;
    asm("mov.b64 %0, {%1, %2};" : "=l"(r) : "f"(x), "f"(y));
    return r;
}
__device__ __forceinline__ float2 upk2(uint64_t v) {
    float2 r;
    asm("mov.b64 {%0, %1}, %2;" : "=f"(r.x), "=f"(r.y) : "l"(v));
    return r;
}
__device__ __forceinline__ void fma2(uint64_t& d, uint64_t a, uint64_t b) {
    asm("fma.rn.f32x2 %0, %1, %2, %0;" : "+l"(d) : "l"(a), "l"(b));
}

// ------------------------------------------------------------ cp.async
__device__ __forceinline__ void cpa16(float4* dst_smem, const float4* src) {
    uint32_t d = (uint32_t)__cvta_generic_to_shared(dst_smem);
    asm volatile("cp.async.ca.shared.global [%0], [%1], 16;"
                 :: "r"(d), "l"(src) : "memory");
}
#define CPA_COMMIT() asm volatile("cp.async.commit_group;" ::: "memory")
#define CPA_WAIT0()  asm volatile("cp.async.wait_group 0;" ::: "memory")

__device__ __forceinline__ void stage_async(float* dst, const float* src,
                                            int nf4, int tid) {
    float4* d = (float4*)dst;
    const float4* s = (const float4*)src;
    for (int e = tid; e < nf4; e += 256) cpa16(d + e, s + e);
}
__device__ __forceinline__ void prefetch_l2(const void* p) {
    asm volatile("prefetch.global.L2 [%0];" :: "l"(p));
}

// ------------------------------------------------------------------- prep
__global__ void k_prep(const float* __restrict__ W2, const float* __restrict__ W3,
                       const float* __restrict__ Wp) {
    int stride = gridDim.x * blockDim.x;
    int i0 = blockIdx.x * blockDim.x + threadIdx.x;
    for (int e = i0; e < 128 * 256; e += stride) {
        int k = e >> 8, n = e & 255;
        g_W2T[e] = W2[n * H1C + k];
    }
    for (int e = i0; e < 256 * 208; e += stride) {
        int k = e / 208, n = e % 208;
        g_W3T[e] = (n < 200) ? W3[n * H2C + k] : 0.f;
    }
    for (int e = i0; e < 200 * 104; e += stride) {
        int k = e / 104, n = e % 104;
        g_WpT[e] = (n < 100) ? Wp[n * H3C + k] : 0.f;
    }
}

// ------------------------------------------------------------- fused kernel
// 64 rows/CTA, 256 threads (8 warps x 8 rows), 2 CTAs/SM.
// Col-pair u64 accumulators; cp.async double-buffered panels; ragged tail
// groups replaced by full-lane "extra accumulator" remainder FFMA2s.
__global__ __launch_bounds__(256, 2) void k_fused(
        const float* __restrict__ x0,   const float* __restrict__ W1,
        const float* __restrict__ b1,   const float* __restrict__ b2,
        const float* __restrict__ b3,
        const float* __restrict__ gumbel, const float* __restrict__ rnd,
        const float* __restrict__ Wmu,  const float* __restrict__ bmu,
        const float* __restrict__ Wsig, const float* __restrict__ bsig,
        const float* __restrict__ bpai, float* __restrict__ out) {
    extern __shared__ float sm[];
    float* h1s = sm;
    float* h2s = sm;
    float* h3s = sm;
    float* WBa = sm + 16384;
    float* WBb = sm + 20544;
    float* lps = sm + 16384;
    __shared__ float xs[64 * 3], W1s[H1C * 3], b1s[H1C], b2s[H2C], b3s[H3C], bps[GDC];
    __shared__ int idxs[256];

    const int tid  = threadIdx.x;
    const int wid  = tid >> 5, lane = tid & 31;
    const int b0   = blockIdx.x * 64;
    const int r0   = wid * 8;

    // ---- stage constants; prefetch W2 panel 0; L2-prefetch gumbel slice
    for (int e = tid; e < H1C * 3; e += 256) W1s[e] = W1[e];
    if (tid < H1C) b1s[tid] = b1[tid];
    b2s[tid] = b2[tid];
    for (int e = tid; e < H3C; e += 256) b3s[e] = b3[e];
    for (int e = tid; e < GDC; e += 256) bps[e] = bpai[e];
    for (int e = tid; e < 64 * 3; e += 256) xs[e] = x0[(size_t)b0 * 3 + e];
    stage_async(WBa, g_W2T, 1024, tid);
    CPA_COMMIT();
    if (tid < 200) prefetch_l2(gumbel + (size_t)b0 * GDC + tid * 32);
    __syncthreads();   // constants ready

    // ---- layer 1: h1 = relu(x0 @ W1^T + b1)
    for (int e = tid; e < 64 * H1C; e += 256) {
        int r = e >> 7, j = e & 127;
        float v = fmaf(xs[r * 3 + 0], W1s[j * 3 + 0],
                  fmaf(xs[r * 3 + 1], W1s[j * 3 + 1],
                  fmaf(xs[r * 3 + 2], W1s[j * 3 + 2], b1s[j])));
        h1s[e] = fmaxf(v, 0.f);
    }

    // =========== layer 2: [64 x 256], K=128, 8 panels of 16 k ============
    uint64_t acc2[8][4];
#pragma unroll
    for (int r = 0; r < 8; r++)
#pragma unroll
        for (int j = 0; j < 4; j++) acc2[r][j] = 0ull;

    for (int p = 0; p < 8; p++) {
        CPA_WAIT0();
        __syncthreads();   // panel p ready; (p=0: h1s ready too)
        if (p < 7) {
            stage_async((p & 1) ? WBa : WBb, g_W2T + (p + 1) * 16 * 256, 1024, tid);
            CPA_COMMIT();
        }
        const float* wb = (p & 1) ? WBb : WBa;
        const uint64_t* bptr = (const uint64_t*)wb + lane;
        const float*    aptr = h1s + r0 * H1C + p * 16;
#pragma unroll 4
        for (int k = 0; k < 16; k++) {
            uint64_t bv0 = bptr[0], bv1 = bptr[32];
            uint64_t bv2 = bptr[64], bv3 = bptr[96];
#pragma unroll
            for (int r = 0; r < 8; r++) {
                float av = aptr[r * H1C];
                uint64_t a2 = pk2(av, av);
                fma2(acc2[r][0], a2, bv0);
                fma2(acc2[r][1], a2, bv1);
                fma2(acc2[r][2], a2, bv2);
                fma2(acc2[r][3], a2, bv3);
            }
            bptr += 128; aptr += 1;
        }
    }
    __syncthreads();   // l2 compute done -> safe to overlay h1s & stage l3

    stage_async(WBa, g_W3T, 832, tid);   // l3 panel 0
    CPA_COMMIT();

    // epilogue: h2 = relu(acc + b2); cols n = 64j + 2*lane
#pragma unroll
    for (int r = 0; r < 8; r++)
#pragma unroll
        for (int j = 0; j < 4; j++) {
            int n = 64 * j + 2 * lane;
            float2 v = upk2(acc2[r][j]);
            v.x = fmaxf(v.x + b2s[n],     0.f);
            v.y = fmaxf(v.y + b2s[n + 1], 0.f);
            *(float2*)(h2s + (r0 + r) * H2C + n) = v;
        }

    // ====== layer 3: [64 x 200], K=256, 16 panels of 16 k =================
    // j=0..2 -> cols 0..191 (full lanes); extra acc -> cols 192..199:
    // lane = 4*row_in_warp + pair_in_4 (8 rows x 4 pairs = 32 lanes, exact).
    uint64_t acc3[8][3];
#pragma unroll
    for (int r = 0; r < 8; r++)
#pragma unroll
        for (int j = 0; j < 3; j++) acc3[r][j] = 0ull;
    uint64_t acc3E = 0ull;
    const int e3row = lane >> 2;            // 0..7
    const int e3pair = lane & 3;            // 0..3  -> col pair 96..99

    for (int p = 0; p < 16; p++) {
        CPA_WAIT0();
        __syncthreads();   // panel p ready; (p=0: h2s ready too)
        if (p < 15) {
            stage_async((p & 1) ? WBa : WBb, g_W3T + (p + 1) * 16 * 208, 832, tid);
            CPA_COMMIT();
        }
        const float* wb = (p & 1) ? WBb : WBa;
        const uint64_t* bptr  = (const uint64_t*)wb + lane;
        const uint64_t* bptrE = (const uint64_t*)wb + 96 + e3pair;
        const float*    aptr  = h2s + r0 * H2C + p * 16;
        const float*    aptrE = h2s + (r0 + e3row) * H2C + p * 16;
#pragma unroll 4
        for (int k = 0; k < 16; k++) {
            uint64_t bv0 = bptr[0], bv1 = bptr[32], bv2 = bptr[64];
#pragma unroll
            for (int r = 0; r < 8; r++) {
                float av = aptr[r * H2C];
                uint64_t a2 = pk2(av, av);
                fma2(acc3[r][0], a2, bv0);
                fma2(acc3[r][1], a2, bv1);
                fma2(acc3[r][2], a2, bv2);
            }
            {
                float avE = aptrE[0];
                uint64_t a2E = pk2(avE, avE);
                fma2(acc3E, a2E, bptrE[0]);
            }
            bptr += 104; bptrE += 104; aptr += 1; aptrE += 1;
        }
    }
    __syncthreads();   // l3 compute done -> safe to overlay h2s & stage pi

    stage_async(WBa, g_WpT, 1040, tid);  // pi panel 0
    CPA_COMMIT();

    // epilogue: h3 = relu(acc + b3)
#pragma unroll
    for (int r = 0; r < 8; r++)
#pragma unroll
        for (int j = 0; j < 3; j++) {
            int n = 64 * j + 2 * lane;
            float2 v = upk2(acc3[r][j]);
            v.x = fmaxf(v.x + b3s[n],     0.f);
            v.y = fmaxf(v.y + b3s[n + 1], 0.f);
            *(float2*)(h3s + (r0 + r) * H3C + n) = v;
        }
    {   // extra: cols 192..199, row r0 + e3row
        int n = 192 + 2 * e3pair;
        float2 v = upk2(acc3E);
        v.x = fmaxf(v.x + b3s[n],     0.f);
        v.y = fmaxf(v.y + b3s[n + 1], 0.f);
        *(float2*)(h3s + (r0 + e3row) * H3C + n) = v;
    }

    // ============ pi GEMM: [64 x 100], K=200, 5 panels of 40 k ============
    // j=0 -> cols 0..63 (full lanes); 5 extra accs -> pairs 32..49
    // (cols 64..99): unit u = 32e + lane, row = u/18, pair = 32 + u%18.
    uint64_t accp[8];
#pragma unroll
    for (int r = 0; r < 8; r++) accp[r] = 0ull;
    uint64_t accpE[5];
    int epRow[5], epOff[5];
    bool epOk[5];
#pragma unroll
    for (int e = 0; e < 5; e++) {
        accpE[e] = 0ull;
        int u = 32 * e + lane;
        epOk[e]  = (u < 144);
        int ru   = epOk[e] ? (u / 18) : 7;
        epRow[e] = ru;
        epOff[e] = 32 + (epOk[e] ? (u % 18) : 0);
    }

    for (int p = 0; p < 5; p++) {
        CPA_WAIT0();
        __syncthreads();   // panel p ready; (p=0: h3s ready too)
        if (p < 4) {
            stage_async((p & 1) ? WBa : WBb, g_WpT + (p + 1) * 40 * 104, 1040, tid);
            CPA_COMMIT();
        }
        const float* wb = (p & 1) ? WBb : WBa;
        const uint64_t* bptr  = (const uint64_t*)wb + lane;
        const uint64_t* bptrE = (const uint64_t*)wb;
        const float*    aptr  = h3s + r0 * H3C + p * 40;
        const float*    aE0   = h3s + (r0 + epRow[0]) * H3C + p * 40;
        const float*    aE1   = h3s + (r0 + epRow[1]) * H3C + p * 40;
        const float*    aE2   = h3s + (r0 + epRow[2]) * H3C + p * 40;
        const float*    aE3   = h3s + (r0 + epRow[3]) * H3C + p * 40;
        const float*    aE4   = h3s + (r0 + epRow[4]) * H3C + p * 40;
#pragma unroll 4
        for (int k = 0; k < 40; k++) {
            uint64_t bv0 = bptr[0];
#pragma unroll
            for (int r = 0; r < 8; r++) {
                float av = aptr[r * H3C];
                uint64_t a2 = pk2(av, av);
                fma2(accp[r], a2, bv0);
            }
            {
                float a0 = aE0[0], a1 = aE1[0], a2v = aE2[0], a3 = aE3[0], a4 = aE4[0];
                fma2(accpE[0], pk2(a0, a0), bptrE[epOff[0]]);
                fma2(accpE[1], pk2(a1, a1), bptrE[epOff[1]]);
                fma2(accpE[2], pk2(a2v, a2v), bptrE[epOff[2]]);
                fma2(accpE[3], pk2(a3, a3), bptrE[epOff[3]]);
                fma2(accpE[4], pk2(a4, a4), bptrE[epOff[4]]);
            }
            bptr += 52; bptrE += 52; aptr += 1;
            aE0 += 1; aE1 += 1; aE2 += 1; aE3 += 1; aE4 += 1;
        }
    }
    __syncthreads();   // pi reads of WB done -> lps may overlay WB

    // lps = log(|pi + b| + eps)
#pragma unroll
    for (int r = 0; r < 8; r++) {
        int n = 2 * lane;
        float2 v = upk2(accp[r]);
        float2 o;
        o.x = logf(fabsf(v.x + bps[n])     + 1e-12f);
        o.y = logf(fabsf(v.y + bps[n + 1]) + 1e-12f);
        *(float2*)(lps + (r0 + r) * GDC + n) = o;
    }
#pragma unroll
    for (int e = 0; e < 5; e++) {
        if (epOk[e]) {
            int n = 2 * epOff[e];               // 64..98
            float2 v = upk2(accpE[e]);
            float2 o;
            o.x = logf(fabsf(v.x + bps[n])     + 1e-12f);
            o.y = logf(fabsf(v.y + bps[n + 1]) + 1e-12f);
            *(float2*)(lps + (r0 + epRow[e]) * GDC + n) = o;
        }
    }
    __syncthreads();

    // ---- Gumbel-argmax per (row, d)
    {
        int r = tid >> 2, d = tid & 3;
        const float* gp = gumbel + (size_t)(b0 + r) * GDC + d;
        float best = -1e30f;
        int bg = 0;
#pragma unroll
        for (int g = 0; g < GC; g++) {
            float v = lps[r * GDC + g * 4 + d] + gp[g * 4];
            if (v > best) { best = v; bg = g; }
        }
        idxs[tid] = bg;
    }
    __syncthreads();

    // ---- selection: 8 lanes per pair, 4 pairs per warp per iter, 8 iters
    const int sl = lane & 7, grp = lane >> 3;
    for (int it = 0; it < 8; it++) {
        int pp = wid * 32 + it * 4 + grp;
        int r = pp >> 2, d = pp & 3;
        int head = idxs[pp] * 4 + d;
        const float4* wm = (const float4*)(Wmu  + (size_t)head * H3C);
        const float4* ws = (const float4*)(Wsig + (size_t)head * H3C);
        const float4* hv = (const float4*)(h3s + r * H3C);

        float smu = 0.f, ssg = 0.f;
#pragma unroll
        for (int j = 0; j < 6; j++) {
            int i4 = sl + 8 * j;
            float4 h = hv[i4];
            float4 m = wm[i4];
            float4 s = ws[i4];
            smu = fmaf(h.x, m.x, fmaf(h.y, m.y, fmaf(h.z, m.z, fmaf(h.w, m.w, smu))));
            ssg = fmaf(h.x, s.x, fmaf(h.y, s.y, fmaf(h.z, s.z, fmaf(h.w, s.w, ssg))));
        }
        if (sl < 2) {
            int i4 = 48 + sl;
            float4 h = hv[i4];
            float4 m = wm[i4];
            float4 s = ws[i4];
            smu = fmaf(h.x, m.x, fmaf(h.y, m.y, fmaf(h.z, m.z, fmaf(h.w, m.w, smu))));
            ssg = fmaf(h.x, s.x, fmaf(h.y, s.y, fmaf(h.z, s.z, fmaf(h.w, s.w, ssg))));
        }
#pragma unroll
        for (int off = 4; off > 0; off >>= 1) {
            smu += __shfl_xor_sync(0xffffffffu, smu, off);
            ssg += __shfl_xor_sync(0xffffffffu, ssg, off);
        }
        if (sl == 0) {
            float mu = smu + bmu[head];
            float sg = fabsf(ssg + bsig[head]);
            size_t oi = (size_t)(b0 + r) * DC + d;
            out[oi] = rnd[oi] * sg + mu;
        }
    }
}

// ---------------------------------------------------------------- launch
extern "C" void kernel_launch(void* const* d_in, const int* in_sizes, int n_in,
                              void* d_out, int out_size) {
    const float* x0   = (const float*)d_in[0];
    const float* rnd  = (const float*)d_in[1];
    const float* gum  = (const float*)d_in[2];
    const float* W1   = (const float*)d_in[3];
    const float* b1   = (const float*)d_in[4];
    const float* W2   = (const float*)d_in[5];
    const float* b2   = (const float*)d_in[6];
    const float* W3   = (const float*)d_in[7];
    const float* b3   = (const float*)d_in[8];
    const float* Wmu  = (const float*)d_in[9];
    const float* bmu  = (const float*)d_in[10];
    const float* Wsig = (const float*)d_in[11];
    const float* bsig = (const float*)d_in[12];
    const float* Wpai = (const float*)d_in[13];
    const float* bpai = (const float*)d_in[14];
    float* out = (float*)d_out;

    const size_t smF = 24704 * sizeof(float);   // 98816 B -> 2 CTAs/SM

    cudaFuncSetAttribute(k_fused, cudaFuncAttributeMaxDynamicSharedMemorySize, (int)smF);

    k_prep <<<64, 256>>>(W2, W3, Wpai);
    k_fused<<<NB / 64, 256, smF>>>(x0, W1, b1, b2, b3,
                                   gum, rnd, Wmu, bmu, Wsig, bsig, bpai, out);
}

// round 14
// speedup vs baseline: 1.0065x; 1.0065x over previous
#include <cuda_runtime.h>
#include <math.h>
#include <stdint.h>

#define NB   262144
#define H1C  128
#define H2C  256
#define H3C  200
#define GC   25
#define DC   4
#define GDC  100
#define S2   260       // padded h2s row stride (bank-skew 4)
#define S3   204       // padded h3s row stride (bank-skew 12)

// ---------------------------------------------------------- device scratch
__device__ float g_W2T[128 * 256];      // [k][n]
__device__ float g_W3T[256 * 208];      // [k][n], n padded 200->208
__device__ float g_WpT[200 * 104];      // [k][n], n padded 100->104

// ------------------------------------------------------------ f32x2 helpers
__device__ __forceinline__ uint64_t pk2(float x, float y) {
    uint64_t r;
    asm("mov.b64 %0, {%1, %2};" : "=l"(r) : "f"(x), "f"(y));
    return r;
}
__device__ __forceinline__ float2 upk2(uint64_t v) {
    float2 r;
    asm("mov.b64 {%0, %1}, %2;" : "=f"(r.x), "=f"(r.y) : "l"(v));
    return r;
}
__device__ __forceinline__ void fma2(uint64_t& d, uint64_t a, uint64_t b) {
    asm("fma.rn.f32x2 %0, %1, %2, %0;" : "+l"(d) : "l"(a), "l"(b));
}

// ------------------------------------------------------------ cp.async
__device__ __forceinline__ void cpa16(float4* dst_smem, const float4* src) {
    uint32_t d = (uint32_t)__cvta_generic_to_shared(dst_smem);
    asm volatile("cp.async.ca.shared.global [%0], [%1], 16;"
                 :: "r"(d), "l"(src) : "memory");
}
#define CPA_COMMIT() asm volatile("cp.async.commit_group;" ::: "memory")
#define CPA_WAIT0()  asm volatile("cp.async.wait_group 0;" ::: "memory")

__device__ __forceinline__ void stage_async(float* dst, const float* src,
                                            int nf4, int tid) {
    float4* d = (float4*)dst;
    const float4* s = (const float4*)src;
    for (int e = tid; e < nf4; e += 256) cpa16(d + e, s + e);
}
__device__ __forceinline__ void prefetch_l2(const void* p) {
    asm volatile("prefetch.global.L2 [%0];" :: "l"(p));
}

// ------------------------------------------------------------------- prep
__global__ void k_prep(const float* __restrict__ W2, const float* __restrict__ W3,
                       const float* __restrict__ Wp) {
    int stride = gridDim.x * blockDim.x;
    int i0 = blockIdx.x * blockDim.x + threadIdx.x;
    for (int e = i0; e < 128 * 256; e += stride) {
        int k = e >> 8, n = e & 255;
        g_W2T[e] = W2[n * H1C + k];
    }
    for (int e = i0; e < 256 * 208; e += stride) {
        int k = e / 208, n = e % 208;
        g_W3T[e] = (n < 200) ? W3[n * H2C + k] : 0.f;
    }
    for (int e = i0; e < 200 * 104; e += stride) {
        int k = e / 104, n = e % 104;
        g_WpT[e] = (n < 100) ? Wp[n * H3C + k] : 0.f;
    }
}

// ------------------------------------------------------------- fused kernel
// 64 rows/CTA, 256 threads (8 warps x 8 rows), 2 CTAs/SM.
// Col-pair u64 accumulators; cp.async double-buffered panels; full-lane
// tail groups with PADDED activation strides (conflict-free per-row loads).
__global__ __launch_bounds__(256, 2) void k_fused(
        const float* __restrict__ x0,   const float* __restrict__ W1,
        const float* __restrict__ b1,   const float* __restrict__ b2,
        const float* __restrict__ b3,
        const float* __restrict__ gumbel, const float* __restrict__ rnd,
        const float* __restrict__ Wmu,  const float* __restrict__ bmu,
        const float* __restrict__ Wsig, const float* __restrict__ bsig,
        const float* __restrict__ bpai, float* __restrict__ out) {
    extern __shared__ float sm[];
    float* h1s = sm;                   // [64][128]
    float* h2s = sm;                   // [64][S2] overlay
    float* h3s = sm;                   // [64][S3] overlay
    float* WBa = sm + 16640;           // 4160 floats
    float* WBb = sm + 20800;           // 4160 floats
    float* lps = sm + 16640;           // [64][100] overlays WB after pi
    __shared__ float xs[64 * 3], W1s[H1C * 3], b1s[H1C], b2s[H2C], b3s[H3C], bps[GDC];
    __shared__ int idxs[256];

    const int tid  = threadIdx.x;
    const int wid  = tid >> 5, lane = tid & 31;
    const int b0   = blockIdx.x * 64;
    const int r0   = wid * 8;

    // ---- stage constants; prefetch W2 panel 0; L2-prefetch gumbel slice
    for (int e = tid; e < H1C * 3; e += 256) W1s[e] = W1[e];
    if (tid < H1C) b1s[tid] = b1[tid];
    b2s[tid] = b2[tid];
    for (int e = tid; e < H3C; e += 256) b3s[e] = b3[e];
    for (int e = tid; e < GDC; e += 256) bps[e] = bpai[e];
    for (int e = tid; e < 64 * 3; e += 256) xs[e] = x0[(size_t)b0 * 3 + e];
    stage_async(WBa, g_W2T, 1024, tid);
    CPA_COMMIT();
    if (tid < 200) prefetch_l2(gumbel + (size_t)b0 * GDC + tid * 32);
    __syncthreads();   // constants ready

    // ---- layer 1: h1 = relu(x0 @ W1^T + b1)
    for (int e = tid; e < 64 * H1C; e += 256) {
        int r = e >> 7, j = e & 127;
        float v = fmaf(xs[r * 3 + 0], W1s[j * 3 + 0],
                  fmaf(xs[r * 3 + 1], W1s[j * 3 + 1],
                  fmaf(xs[r * 3 + 2], W1s[j * 3 + 2], b1s[j])));
        h1s[e] = fmaxf(v, 0.f);
    }

    // =========== layer 2: [64 x 256], K=128, 8 panels of 16 k ============
    uint64_t acc2[8][4];
#pragma unroll
    for (int r = 0; r < 8; r++)
#pragma unroll
        for (int j = 0; j < 4; j++) acc2[r][j] = 0ull;

    for (int p = 0; p < 8; p++) {
        CPA_WAIT0();
        __syncthreads();   // panel p ready; (p=0: h1s ready too)
        if (p < 7) {
            stage_async((p & 1) ? WBa : WBb, g_W2T + (p + 1) * 16 * 256, 1024, tid);
            CPA_COMMIT();
        }
        const float* wb = (p & 1) ? WBb : WBa;
        const uint64_t* bptr = (const uint64_t*)wb + lane;
        const float*    aptr = h1s + r0 * H1C + p * 16;
#pragma unroll 4
        for (int k = 0; k < 16; k++) {
            uint64_t bv0 = bptr[0], bv1 = bptr[32];
            uint64_t bv2 = bptr[64], bv3 = bptr[96];
#pragma unroll
            for (int r = 0; r < 8; r++) {
                float av = aptr[r * H1C];
                uint64_t a2 = pk2(av, av);
                fma2(acc2[r][0], a2, bv0);
                fma2(acc2[r][1], a2, bv1);
                fma2(acc2[r][2], a2, bv2);
                fma2(acc2[r][3], a2, bv3);
            }
            bptr += 128; aptr += 1;
        }
    }
    __syncthreads();   // l2 compute done -> safe to overlay h1s & stage l3

    stage_async(WBa, g_W3T, 832, tid);   // l3 panel 0
    CPA_COMMIT();

    // epilogue: h2 = relu(acc + b2); cols n = 64j + 2*lane, row stride S2
#pragma unroll
    for (int r = 0; r < 8; r++)
#pragma unroll
        for (int j = 0; j < 4; j++) {
            int n = 64 * j + 2 * lane;
            float2 v = upk2(acc2[r][j]);
            v.x = fmaxf(v.x + b2s[n],     0.f);
            v.y = fmaxf(v.y + b2s[n + 1], 0.f);
            *(float2*)(h2s + (r0 + r) * S2 + n) = v;
        }

    // ====== layer 3: [64 x 200], K=256, 16 panels of 16 k =================
    // j=0..2 -> cols 0..191 (full lanes); tail acc -> cols 192..199:
    // lane = 4*row + pair (8 rows x 4 pairs = 32 lanes, exact).
    uint64_t acc3[8][3];
#pragma unroll
    for (int r = 0; r < 8; r++)
#pragma unroll
        for (int j = 0; j < 3; j++) acc3[r][j] = 0ull;
    uint64_t acc3E = 0ull;
    const int e3row  = lane >> 2;           // 0..7
    const int e3pair = lane & 3;            // 0..3 -> col pair 96..99

    for (int p = 0; p < 16; p++) {
        CPA_WAIT0();
        __syncthreads();   // panel p ready; (p=0: h2s ready too)
        if (p < 15) {
            stage_async((p & 1) ? WBa : WBb, g_W3T + (p + 1) * 16 * 208, 832, tid);
            CPA_COMMIT();
        }
        const float* wb = (p & 1) ? WBb : WBa;
        const uint64_t* bptr  = (const uint64_t*)wb + lane;
        const uint64_t* bptrE = (const uint64_t*)wb + 96 + e3pair;
        const float*    aptr  = h2s + r0 * S2 + p * 16;
        const float*    aptrE = h2s + (r0 + e3row) * S2 + p * 16;  // banks 4r
#pragma unroll 4
        for (int k = 0; k < 16; k++) {
            uint64_t bv0 = bptr[0], bv1 = bptr[32], bv2 = bptr[64];
#pragma unroll
            for (int r = 0; r < 8; r++) {
                float av = aptr[r * S2];
                uint64_t a2 = pk2(av, av);
                fma2(acc3[r][0], a2, bv0);
                fma2(acc3[r][1], a2, bv1);
                fma2(acc3[r][2], a2, bv2);
            }
            {
                float avE = aptrE[0];
                uint64_t a2E = pk2(avE, avE);
                fma2(acc3E, a2E, bptrE[0]);
            }
            bptr += 104; bptrE += 104; aptr += 1; aptrE += 1;
        }
    }
    __syncthreads();   // l3 compute done -> safe to overlay h2s & stage pi

    stage_async(WBa, g_WpT, 1040, tid);  // pi panel 0
    CPA_COMMIT();

    // epilogue: h3 = relu(acc + b3), row stride S3
#pragma unroll
    for (int r = 0; r < 8; r++)
#pragma unroll
        for (int j = 0; j < 3; j++) {
            int n = 64 * j + 2 * lane;
            float2 v = upk2(acc3[r][j]);
            v.x = fmaxf(v.x + b3s[n],     0.f);
            v.y = fmaxf(v.y + b3s[n + 1], 0.f);
            *(float2*)(h3s + (r0 + r) * S3 + n) = v;
        }
    {   // tail: cols 192..199, row r0 + e3row
        int n = 192 + 2 * e3pair;
        float2 v = upk2(acc3E);
        v.x = fmaxf(v.x + b3s[n],     0.f);
        v.y = fmaxf(v.y + b3s[n + 1], 0.f);
        *(float2*)(h3s + (r0 + e3row) * S3 + n) = v;
    }

    // ============ pi GEMM: [64 x 100], K=200, 5 panels of 40 k ============
    // j=0 -> cols 0..63 (full lanes); 5 tail accs -> pairs 32..49:
    // unit u = 32e + lane, row = u/18, pair = 32 + u%18 (u < 144).
    uint64_t accp[8];
#pragma unroll
    for (int r = 0; r < 8; r++) accp[r] = 0ull;
    uint64_t accpE[5];
    int epRow[5], epOff[5];
    bool epOk[5];
#pragma unroll
    for (int e = 0; e < 5; e++) {
        accpE[e] = 0ull;
        int u = 32 * e + lane;
        epOk[e]  = (u < 144);
        epRow[e] = epOk[e] ? (u / 18) : 7;
        epOff[e] = 32 + (epOk[e] ? (u % 18) : 0);
    }

    for (int p = 0; p < 5; p++) {
        CPA_WAIT0();
        __syncthreads();   // panel p ready; (p=0: h3s ready too)
        if (p < 4) {
            stage_async((p & 1) ? WBa : WBb, g_WpT + (p + 1) * 40 * 104, 1040, tid);
            CPA_COMMIT();
        }
        const float* wb = (p & 1) ? WBb : WBa;
        const uint64_t* bptr  = (const uint64_t*)wb + lane;
        const uint64_t* bptrE = (const uint64_t*)wb;
        const float*    aptr  = h3s + r0 * S3 + p * 40;
        const float*    aE0   = h3s + (r0 + epRow[0]) * S3 + p * 40;  // banks 12r
        const float*    aE1   = h3s + (r0 + epRow[1]) * S3 + p * 40;
        const float*    aE2   = h3s + (r0 + epRow[2]) * S3 + p * 40;
        const float*    aE3   = h3s + (r0 + epRow[3]) * S3 + p * 40;
        const float*    aE4   = h3s + (r0 + epRow[4]) * S3 + p * 40;
#pragma unroll 4
        for (int k = 0; k < 40; k++) {
            uint64_t bv0 = bptr[0];
#pragma unroll
            for (int r = 0; r < 8; r++) {
                float av = aptr[r * S3];
                uint64_t a2 = pk2(av, av);
                fma2(accp[r], a2, bv0);
            }
            {
                float a0 = aE0[0], a1 = aE1[0], a2v = aE2[0], a3 = aE3[0], a4 = aE4[0];
                fma2(accpE[0], pk2(a0, a0),   bptrE[epOff[0]]);
                fma2(accpE[1], pk2(a1, a1),   bptrE[epOff[1]]);
                fma2(accpE[2], pk2(a2v, a2v), bptrE[epOff[2]]);
                fma2(accpE[3], pk2(a3, a3),   bptrE[epOff[3]]);
                fma2(accpE[4], pk2(a4, a4),   bptrE[epOff[4]]);
            }
            bptr += 52; bptrE += 52; aptr += 1;
            aE0 += 1; aE1 += 1; aE2 += 1; aE3 += 1; aE4 += 1;
        }
    }
    __syncthreads();   // pi reads of WB done -> lps may overlay WB

    // lps = log(|pi + b| + eps)
#pragma unroll
    for (int r = 0; r < 8; r++) {
        int n = 2 * lane;
        float2 v = upk2(accp[r]);
        float2 o;
        o.x = logf(fabsf(v.x + bps[n])     + 1e-12f);
        o.y = logf(fabsf(v.y + bps[n + 1]) + 1e-12f);
        *(float2*)(lps + (r0 + r) * GDC + n) = o;
    }
#pragma unroll
    for (int e = 0; e < 5; e++) {
        if (epOk[e]) {
            int n = 2 * epOff[e];               // 64..98
            float2 v = upk2(accpE[e]);
            float2 o;
            o.x = logf(fabsf(v.x + bps[n])     + 1e-12f);
            o.y = logf(fabsf(v.y + bps[n + 1]) + 1e-12f);
            *(float2*)(lps + (r0 + epRow[e]) * GDC + n) = o;
        }
    }
    __syncthreads();

    // ---- Gumbel-argmax per (row, d)
    {
        int r = tid >> 2, d = tid & 3;
        const float* gp = gumbel + (size_t)(b0 + r) * GDC + d;
        float best = -1e30f;
        int bg = 0;
#pragma unroll
        for (int g = 0; g < GC; g++) {
            float v = lps[r * GDC + g * 4 + d] + gp[g * 4];
            if (v > best) { best = v; bg = g; }
        }
        idxs[tid] = bg;
    }
    __syncthreads();

    // ---- selection: 8 lanes per pair, 4 pairs per warp per iter, 8 iters
    const int sl = lane & 7, grp = lane >> 3;
    for (int it = 0; it < 8; it++) {
        int pp = wid * 32 + it * 4 + grp;
        int r = pp >> 2, d = pp & 3;
        int head = idxs[pp] * 4 + d;
        const float4* wm = (const float4*)(Wmu  + (size_t)head * H3C);
        const float4* ws = (const float4*)(Wsig + (size_t)head * H3C);
        const float4* hv = (const float4*)(h3s + r * S3);

        float smu = 0.f, ssg = 0.f;
#pragma unroll
        for (int j = 0; j < 6; j++) {
            int i4 = sl + 8 * j;
            float4 h = hv[i4];
            float4 m = wm[i4];
            float4 s = ws[i4];
            smu = fmaf(h.x, m.x, fmaf(h.y, m.y, fmaf(h.z, m.z, fmaf(h.w, m.w, smu))));
            ssg = fmaf(h.x, s.x, fmaf(h.y, s.y, fmaf(h.z, s.z, fmaf(h.w, s.w, ssg))));
        }
        if (sl < 2) {
            int i4 = 48 + sl;
            float4 h = hv[i4];
            float4 m = wm[i4];
            float4 s = ws[i4];
            smu = fmaf(h.x, m.x, fmaf(h.y, m.y, fmaf(h.z, m.z, fmaf(h.w, m.w, smu))));
            ssg = fmaf(h.x, s.x, fmaf(h.y, s.y, fmaf(h.z, s.z, fmaf(h.w, s.w, ssg))));
        }
#pragma unroll
        for (int off = 4; off > 0; off >>= 1) {
            smu += __shfl_xor_sync(0xffffffffu, smu, off);
            ssg += __shfl_xor_sync(0xffffffffu, ssg, off);
        }
        if (sl == 0) {
            float mu = smu + bmu[head];
            float sg = fabsf(ssg + bsig[head]);
            size_t oi = (size_t)(b0 + r) * DC + d;
            out[oi] = rnd[oi] * sg + mu;
        }
    }
}

// ---------------------------------------------------------------- launch
extern "C" void kernel_launch(void* const* d_in, const int* in_sizes, int n_in,
                              void* d_out, int out_size) {
    const float* x0   = (const float*)d_in[0];
    const float* rnd  = (const float*)d_in[1];
    const float* gum  = (const float*)d_in[2];
    const float* W1   = (const float*)d_in[3];
    const float* b1   = (const float*)d_in[4];
    const float* W2   = (const float*)d_in[5];
    const float* b2   = (const float*)d_in[6];
    const float* W3   = (const float*)d_in[7];
    const float* b3   = (const float*)d_in[8];
    const float* Wmu  = (const float*)d_in[9];
    const float* bmu  = (const float*)d_in[10];
    const float* Wsig = (const float*)d_in[11];
    const float* bsig = (const float*)d_in[12];
    const float* Wpai = (const float*)d_in[13];
    const float* bpai = (const float*)d_in[14];
    float* out = (float*)d_out;

    const size_t smF = 24960 * sizeof(float);   // 99840 B -> 2 CTAs/SM

    cudaFuncSetAttribute(k_fused, cudaFuncAttributeMaxDynamicSharedMemorySize, (int)smF);

    k_prep <<<64, 256>>>(W2, W3, Wpai);
    k_fused<<<NB / 64, 256, smF>>>(x0, W1, b1, b2, b3,
                                   gum, rnd, Wmu, bmu, Wsig, bsig, bpai, out);
}

// round 15
// speedup vs baseline: 1.2256x; 1.2177x over previous
#include <cuda_runtime.h>
#include <math.h>
#include <stdint.h>

#define NB   262144
#define H1C  128
#define H2C  256
#define H3C  200
#define GC   25
#define DC   4
#define GDC  100
#define S2   260       // padded h2s row stride (bank-skew 4)

// ---------------------------------------------------------- device scratch
__device__ float g_W2T[128 * 256];      // [k][n]
__device__ float g_W3T[256 * 208];      // [k][n], n padded 200->208
__device__ float g_WpT[200 * 104];      // [k][n], n padded 100->104

// ------------------------------------------------------------ f32x2 helpers
__device__ __forceinline__ uint64_t pk2(float x, float y) {
    uint64_t r;
    asm("mov.b64 %0, {%1, %2};" : "=l"(r) : "f"(x), "f"(y));
    return r;
}
__device__ __forceinline__ float2 upk2(uint64_t v) {
    float2 r;
    asm("mov.b64 {%0, %1}, %2;" : "=f"(r.x), "=f"(r.y) : "l"(v));
    return r;
}
__device__ __forceinline__ void fma2(uint64_t& d, uint64_t a, uint64_t b) {
    asm("fma.rn.f32x2 %0, %1, %2, %0;" : "+l"(d) : "l"(a), "l"(b));
}

// ------------------------------------------------------------ cp.async
__device__ __forceinline__ void cpa16(float4* dst_smem, const float4* src) {
    uint32_t d = (uint32_t)__cvta_generic_to_shared(dst_smem);
    asm volatile("cp.async.ca.shared.global [%0], [%1], 16;"
                 :: "r"(d), "l"(src) : "memory");
}
#define CPA_COMMIT() asm volatile("cp.async.commit_group;" ::: "memory")
#define CPA_WAIT0()  asm volatile("cp.async.wait_group 0;" ::: "memory")

__device__ __forceinline__ void stage_async(float* dst, const float* src,
                                            int nf4, int tid) {
    float4* d = (float4*)dst;
    const float4* s = (const float4*)src;
    for (int e = tid; e < nf4; e += 256) cpa16(d + e, s + e);
}
__device__ __forceinline__ void prefetch_l2(const void* p) {
    asm volatile("prefetch.global.L2 [%0];" :: "l"(p));
}

// ------------------------------------------------------------------- prep
__global__ void k_prep(const float* __restrict__ W2, const float* __restrict__ W3,
                       const float* __restrict__ Wp) {
    int stride = gridDim.x * blockDim.x;
    int i0 = blockIdx.x * blockDim.x + threadIdx.x;
    for (int e = i0; e < 128 * 256; e += stride) {
        int k = e >> 8, n = e & 255;
        g_W2T[e] = W2[n * H1C + k];
    }
    for (int e = i0; e < 256 * 208; e += stride) {
        int k = e / 208, n = e % 208;
        g_W3T[e] = (n < 200) ? W3[n * H2C + k] : 0.f;
    }
    for (int e = i0; e < 200 * 104; e += stride) {
        int k = e / 104, n = e % 104;
        g_WpT[e] = (n < 100) ? Wp[n * H3C + k] : 0.f;
    }
}

// ------------------------------------------------------------- fused kernel
// 64 rows/CTA, 256 threads (8 warps x 8 rows), 2 CTAs/SM.
// Col-pair u64 accumulators; cp.async double-buffered panels; float2
// (2-k) A-loads; l3 full-lane tail group with padded h2s stride.
__global__ __launch_bounds__(256, 2) void k_fused(
        const float* __restrict__ x0,   const float* __restrict__ W1,
        const float* __restrict__ b1,   const float* __restrict__ b2,
        const float* __restrict__ b3,
        const float* __restrict__ gumbel, const float* __restrict__ rnd,
        const float* __restrict__ Wmu,  const float* __restrict__ bmu,
        const float* __restrict__ Wsig, const float* __restrict__ bsig,
        const float* __restrict__ bpai, float* __restrict__ out) {
    extern __shared__ float sm[];
    float* h1s = sm;                   // [64][128]
    float* h2s = sm;                   // [64][S2] overlay
    float* h3s = sm;                   // [64][200] overlay
    float* WBa = sm + 16640;           // 4160 floats
    float* WBb = sm + 20800;           // 4160 floats
    float* lps = sm + 16640;           // [64][100] overlays WB after pi
    __shared__ float xs[64 * 3], W1s[H1C * 3], b1s[H1C], b2s[H2C], b3s[H3C], bps[GDC];
    __shared__ int idxs[256];

    const int tid  = threadIdx.x;
    const int wid  = tid >> 5, lane = tid & 31;
    const int b0   = blockIdx.x * 64;
    const int r0   = wid * 8;

    // ---- stage constants; prefetch W2 panel 0; L2-prefetch gumbel slice
    for (int e = tid; e < H1C * 3; e += 256) W1s[e] = W1[e];
    if (tid < H1C) b1s[tid] = b1[tid];
    b2s[tid] = b2[tid];
    for (int e = tid; e < H3C; e += 256) b3s[e] = b3[e];
    for (int e = tid; e < GDC; e += 256) bps[e] = bpai[e];
    for (int e = tid; e < 64 * 3; e += 256) xs[e] = x0[(size_t)b0 * 3 + e];
    stage_async(WBa, g_W2T, 1024, tid);
    CPA_COMMIT();
    if (tid < 200) prefetch_l2(gumbel + (size_t)b0 * GDC + tid * 32);
    __syncthreads();   // constants ready

    // ---- layer 1: h1 = relu(x0 @ W1^T + b1)
    for (int e = tid; e < 64 * H1C; e += 256) {
        int r = e >> 7, j = e & 127;
        float v = fmaf(xs[r * 3 + 0], W1s[j * 3 + 0],
                  fmaf(xs[r * 3 + 1], W1s[j * 3 + 1],
                  fmaf(xs[r * 3 + 2], W1s[j * 3 + 2], b1s[j])));
        h1s[e] = fmaxf(v, 0.f);
    }

    // =========== layer 2: [64 x 256], K=128, 8 panels of 16 k ============
    uint64_t acc2[8][4];
#pragma unroll
    for (int r = 0; r < 8; r++)
#pragma unroll
        for (int j = 0; j < 4; j++) acc2[r][j] = 0ull;

    for (int p = 0; p < 8; p++) {
        CPA_WAIT0();
        __syncthreads();   // panel p ready; (p=0: h1s ready too)
        if (p < 7) {
            stage_async((p & 1) ? WBa : WBb, g_W2T + (p + 1) * 16 * 256, 1024, tid);
            CPA_COMMIT();
        }
        const float* wb = (p & 1) ? WBb : WBa;
        const uint64_t* bptr = (const uint64_t*)wb + lane;
        const float*    aptr = h1s + r0 * H1C + p * 16;
#pragma unroll 2
        for (int kk = 0; kk < 8; kk++) {          // 2 k per iteration
            float2 av[8];
#pragma unroll
            for (int r = 0; r < 8; r++)
                av[r] = *(const float2*)(aptr + r * H1C);
            {   // k even
                uint64_t bv0 = bptr[0], bv1 = bptr[32];
                uint64_t bv2 = bptr[64], bv3 = bptr[96];
#pragma unroll
                for (int r = 0; r < 8; r++) {
                    uint64_t a2 = pk2(av[r].x, av[r].x);
                    fma2(acc2[r][0], a2, bv0);
                    fma2(acc2[r][1], a2, bv1);
                    fma2(acc2[r][2], a2, bv2);
                    fma2(acc2[r][3], a2, bv3);
                }
            }
            {   // k odd
                uint64_t bv0 = bptr[128], bv1 = bptr[160];
                uint64_t bv2 = bptr[192], bv3 = bptr[224];
#pragma unroll
                for (int r = 0; r < 8; r++) {
                    uint64_t a2 = pk2(av[r].y, av[r].y);
                    fma2(acc2[r][0], a2, bv0);
                    fma2(acc2[r][1], a2, bv1);
                    fma2(acc2[r][2], a2, bv2);
                    fma2(acc2[r][3], a2, bv3);
                }
            }
            bptr += 256; aptr += 2;
        }
    }
    __syncthreads();   // l2 compute done -> safe to overlay h1s & stage l3

    stage_async(WBa, g_W3T, 832, tid);   // l3 panel 0
    CPA_COMMIT();

    // epilogue: h2 = relu(acc + b2); cols n = 64j + 2*lane, row stride S2
#pragma unroll
    for (int r = 0; r < 8; r++)
#pragma unroll
        for (int j = 0; j < 4; j++) {
            int n = 64 * j + 2 * lane;
            float2 v = upk2(acc2[r][j]);
            v.x = fmaxf(v.x + b2s[n],     0.f);
            v.y = fmaxf(v.y + b2s[n + 1], 0.f);
            *(float2*)(h2s + (r0 + r) * S2 + n) = v;
        }

    // ====== layer 3: [64 x 200], K=256, 16 panels of 16 k =================
    // j=0..2 -> cols 0..191 (full lanes); tail acc -> cols 192..199:
    // lane = 4*row + pair (8 rows x 4 pairs = 32 lanes, exact).
    uint64_t acc3[8][3];
#pragma unroll
    for (int r = 0; r < 8; r++)
#pragma unroll
        for (int j = 0; j < 3; j++) acc3[r][j] = 0ull;
    uint64_t acc3E = 0ull;
    const int e3row  = lane >> 2;           // 0..7
    const int e3pair = lane & 3;            // 0..3 -> col pair 96..99

    for (int p = 0; p < 16; p++) {
        CPA_WAIT0();
        __syncthreads();   // panel p ready; (p=0: h2s ready too)
        if (p < 15) {
            stage_async((p & 1) ? WBa : WBb, g_W3T + (p + 1) * 16 * 208, 832, tid);
            CPA_COMMIT();
        }
        const float* wb = (p & 1) ? WBb : WBa;
        const uint64_t* bptr  = (const uint64_t*)wb + lane;
        const uint64_t* bptrE = (const uint64_t*)wb + 96 + e3pair;
        const float*    aptr  = h2s + r0 * S2 + p * 16;
        const float*    aptrE = h2s + (r0 + e3row) * S2 + p * 16;  // banks 4r
#pragma unroll 2
        for (int kk = 0; kk < 8; kk++) {          // 2 k per iteration
            float2 av[8];
#pragma unroll
            for (int r = 0; r < 8; r++)
                av[r] = *(const float2*)(aptr + r * S2);
            float2 avE = *(const float2*)aptrE;
            {   // k even
                uint64_t bv0 = bptr[0], bv1 = bptr[32], bv2 = bptr[64];
#pragma unroll
                for (int r = 0; r < 8; r++) {
                    uint64_t a2 = pk2(av[r].x, av[r].x);
                    fma2(acc3[r][0], a2, bv0);
                    fma2(acc3[r][1], a2, bv1);
                    fma2(acc3[r][2], a2, bv2);
                }
                fma2(acc3E, pk2(avE.x, avE.x), bptrE[0]);
            }
            {   // k odd
                uint64_t bv0 = bptr[104], bv1 = bptr[136], bv2 = bptr[168];
#pragma unroll
                for (int r = 0; r < 8; r++) {
                    uint64_t a2 = pk2(av[r].y, av[r].y);
                    fma2(acc3[r][0], a2, bv0);
                    fma2(acc3[r][1], a2, bv1);
                    fma2(acc3[r][2], a2, bv2);
                }
                fma2(acc3E, pk2(avE.y, avE.y), bptrE[104]);
            }
            bptr += 208; bptrE += 208; aptr += 2; aptrE += 2;
        }
    }
    __syncthreads();   // l3 compute done -> safe to overlay h2s & stage pi

    stage_async(WBa, g_WpT, 1040, tid);  // pi panel 0
    CPA_COMMIT();

    // epilogue: h3 = relu(acc + b3), row stride 200
#pragma unroll
    for (int r = 0; r < 8; r++)
#pragma unroll
        for (int j = 0; j < 3; j++) {
            int n = 64 * j + 2 * lane;
            float2 v = upk2(acc3[r][j]);
            v.x = fmaxf(v.x + b3s[n],     0.f);
            v.y = fmaxf(v.y + b3s[n + 1], 0.f);
            *(float2*)(h3s + (r0 + r) * H3C + n) = v;
        }
    {   // tail: cols 192..199, row r0 + e3row
        int n = 192 + 2 * e3pair;
        float2 v = upk2(acc3E);
        v.x = fmaxf(v.x + b3s[n],     0.f);
        v.y = fmaxf(v.y + b3s[n + 1], 0.f);
        *(float2*)(h3s + (r0 + e3row) * H3C + n) = v;
    }

    // ============ pi GEMM: [64 x 100(104)], K=200, 5 panels of 40 k =======
    uint64_t accp[8][2];
#pragma unroll
    for (int r = 0; r < 8; r++) { accp[r][0] = 0ull; accp[r][1] = 0ull; }

    for (int p = 0; p < 5; p++) {
        CPA_WAIT0();
        __syncthreads();   // panel p ready; (p=0: h3s ready too)
        if (p < 4) {
            stage_async((p & 1) ? WBa : WBb, g_WpT + (p + 1) * 40 * 104, 1040, tid);
            CPA_COMMIT();
        }
        const float* wb = (p & 1) ? WBb : WBa;
        const uint64_t* bptr = (const uint64_t*)wb + lane;
        const float*    aptr = h3s + r0 * H3C + p * 40;
#pragma unroll 2
        for (int kk = 0; kk < 20; kk++) {         // 2 k per iteration
            float2 av[8];
#pragma unroll
            for (int r = 0; r < 8; r++)
                av[r] = *(const float2*)(aptr + r * H3C);
            {   // k even
                uint64_t bv0 = bptr[0];
                uint64_t bv1 = (lane < 20) ? bptr[32] : 0ull;
#pragma unroll
                for (int r = 0; r < 8; r++) {
                    uint64_t a2 = pk2(av[r].x, av[r].x);
                    fma2(accp[r][0], a2, bv0);
                    fma2(accp[r][1], a2, bv1);
                }
            }
            {   // k odd
                uint64_t bv0 = bptr[52];
                uint64_t bv1 = (lane < 20) ? bptr[84] : 0ull;
#pragma unroll
                for (int r = 0; r < 8; r++) {
                    uint64_t a2 = pk2(av[r].y, av[r].y);
                    fma2(accp[r][0], a2, bv0);
                    fma2(accp[r][1], a2, bv1);
                }
            }
            bptr += 104; aptr += 2;
        }
    }
    __syncthreads();   // pi reads of WB done -> lps may overlay WB

    // lps = log(|pi + b| + eps); cols n = 64j + 2*lane (< 100)
#pragma unroll
    for (int r = 0; r < 8; r++) {
        {
            int n = 2 * lane;
            float2 v = upk2(accp[r][0]);
            float2 o;
            o.x = logf(fabsf(v.x + bps[n])     + 1e-12f);
            o.y = logf(fabsf(v.y + bps[n + 1]) + 1e-12f);
            *(float2*)(lps + (r0 + r) * GDC + n) = o;
        }
        if (lane < 18) {
            int n = 64 + 2 * lane;
            float2 v = upk2(accp[r][1]);
            float2 o;
            o.x = logf(fabsf(v.x + bps[n])     + 1e-12f);
            o.y = logf(fabsf(v.y + bps[n + 1]) + 1e-12f);
            *(float2*)(lps + (r0 + r) * GDC + n) = o;
        }
    }
    __syncthreads();

    // ---- Gumbel-argmax per (row, d)
    {
        int r = tid >> 2, d = tid & 3;
        const float* gp = gumbel + (size_t)(b0 + r) * GDC + d;
        float best = -1e30f;
        int bg = 0;
#pragma unroll
        for (int g = 0; g < GC; g++) {
            float v = lps[r * GDC + g * 4 + d] + gp[g * 4];
            if (v > best) { best = v; bg = g; }
        }
        idxs[tid] = bg;
    }
    __syncthreads();

    // ---- selection: 8 lanes per pair, 4 pairs per warp per iter, 8 iters
    const int sl = lane & 7, grp = lane >> 3;
    for (int it = 0; it < 8; it++) {
        int pp = wid * 32 + it * 4 + grp;
        int r = pp >> 2, d = pp & 3;
        int head = idxs[pp] * 4 + d;
        const float4* wm = (const float4*)(Wmu  + (size_t)head * H3C);
        const float4* ws = (const float4*)(Wsig + (size_t)head * H3C);
        const float4* hv = (const float4*)(h3s + r * H3C);

        float smu = 0.f, ssg = 0.f;
#pragma unroll
        for (int j = 0; j < 6; j++) {
            int i4 = sl + 8 * j;
            float4 h = hv[i4];
            float4 m = wm[i4];
            float4 s = ws[i4];
            smu = fmaf(h.x, m.x, fmaf(h.y, m.y, fmaf(h.z, m.z, fmaf(h.w, m.w, smu))));
            ssg = fmaf(h.x, s.x, fmaf(h.y, s.y, fmaf(h.z, s.z, fmaf(h.w, s.w, ssg))));
        }
        if (sl < 2) {
            int i4 = 48 + sl;
            float4 h = hv[i4];
            float4 m = wm[i4];
            float4 s = ws[i4];
            smu = fmaf(h.x, m.x, fmaf(h.y, m.y, fmaf(h.z, m.z, fmaf(h.w, m.w, smu))));
            ssg = fmaf(h.x, s.x, fmaf(h.y, s.y, fmaf(h.z, s.z, fmaf(h.w, s.w, ssg))));
        }
#pragma unroll
        for (int off = 4; off > 0; off >>= 1) {
            smu += __shfl_xor_sync(0xffffffffu, smu, off);
            ssg += __shfl_xor_sync(0xffffffffu, ssg, off);
        }
        if (sl == 0) {
            float mu = smu + bmu[head];
            float sg = fabsf(ssg + bsig[head]);
            size_t oi = (size_t)(b0 + r) * DC + d;
            out[oi] = rnd[oi] * sg + mu;
        }
    }
}

// ---------------------------------------------------------------- launch
extern "C" void kernel_launch(void* const* d_in, const int* in_sizes, int n_in,
                              void* d_out, int out_size) {
    const float* x0   = (const float*)d_in[0];
    const float* rnd  = (const float*)d_in[1];
    const float* gum  = (const float*)d_in[2];
    const float* W1   = (const float*)d_in[3];
    const float* b1   = (const float*)d_in[4];
    const float* W2   = (const float*)d_in[5];
    const float* b2   = (const float*)d_in[6];
    const float* W3   = (const float*)d_in[7];
    const float* b3   = (const float*)d_in[8];
    const float* Wmu  = (const float*)d_in[9];
    const float* bmu  = (const float*)d_in[10];
    const float* Wsig = (const float*)d_in[11];
    const float* bsig = (const float*)d_in[12];
    const float* Wpai = (const float*)d_in[13];
    const float* bpai = (const float*)d_in[14];
    float* out = (float*)d_out;

    const size_t smF = 24960 * sizeof(float);   // 99840 B -> 2 CTAs/SM

    cudaFuncSetAttribute(k_fused, cudaFuncAttributeMaxDynamicSharedMemorySize, (int)smF);

    k_prep <<<64, 256>>>(W2, W3, Wpai);
    k_fused<<<NB / 64, 256, smF>>>(x0, W1, b1, b2, b3,
                                   gum, rnd, Wmu, bmu, Wsig, bsig, bpai, out);
}